// round 3
// baseline (speedup 1.0000x reference)
#include <cuda_runtime.h>
#include <cstdint>

// Inverse 2D Haar wavelet (synthesis), fixed shapes:
//   in : (B=32, C4=256, H=64, W=64) f32   (C4 = C*4: cA,cH,cV,cD per channel)
//   out: (B=32, C=64, 128, 128) f32
//
// Warp processes 4 consecutive input rows of one channel:
//   - per subband: 4x float2 loads per lane (16 front-batched LDG.64 total,
//     each warp-load 256B contiguous; 4 rows = 1KiB contiguous per subband)
//   - stores: 8 consecutive output rows, each STG.128 writes 512B contiguous
//     (4KiB contiguous per warp)

#define IWT_H 64
#define IWT_W 64
#define PLANE_IN  (IWT_H * IWT_W)          // 4096
#define PLANE_OUT (4 * IWT_H * IWT_W)      // 16384
#define ROWS_PER_WARP 4

__global__ void __launch_bounds__(256) iwt_kernel(
    const float* __restrict__ x, float* __restrict__ out)
{
    int t = blockIdx.x * blockDim.x + threadIdx.x;
    int lane = t & 31;
    int w = t >> 5;            // warp id: (bc, hgroup)
    int hg = w & 15;           // 16 groups of 4 rows
    int bc = w >> 4;           // 0 .. 2047
    int h0 = hg * ROWS_PER_WARP;

    // base of subband planes for this channel, at row h0, lane's column pair
    const float* base = x + (size_t)bc * 4 * PLANE_IN + h0 * IWT_W + 2 * lane;

    // Front-batch all 16 loads (4 rows x 4 subbands)
    float2 a[ROWS_PER_WARP], hh[ROWS_PER_WARP], v[ROWS_PER_WARP], d[ROWS_PER_WARP];
#pragma unroll
    for (int r = 0; r < ROWS_PER_WARP; r++)
        a[r] = *(const float2*)(base + r * IWT_W);
#pragma unroll
    for (int r = 0; r < ROWS_PER_WARP; r++)
        hh[r] = *(const float2*)(base + PLANE_IN + r * IWT_W);
#pragma unroll
    for (int r = 0; r < ROWS_PER_WARP; r++)
        v[r] = *(const float2*)(base + 2 * PLANE_IN + r * IWT_W);
#pragma unroll
    for (int r = 0; r < ROWS_PER_WARP; r++)
        d[r] = *(const float2*)(base + 3 * PLANE_IN + r * IWT_W);

    // Output: rows 2*h0 .. 2*h0+7 of channel plane (128x128)
    float* o = out + (size_t)bc * PLANE_OUT + (2 * h0) * (2 * IWT_W) + 4 * lane;

#pragma unroll
    for (int r = 0; r < ROWS_PER_WARP; r++) {
        float4 r0, r1;
        {
            float ai = a[r].x, hi = hh[r].x, vi = v[r].x, di = d[r].x;
            r0.x = (ai + hi + vi + di) * 0.5f;
            r0.y = (ai + hi - vi - di) * 0.5f;
            r1.x = (ai - hi + vi - di) * 0.5f;
            r1.y = (ai - hi - vi + di) * 0.5f;
        }
        {
            float ai = a[r].y, hi = hh[r].y, vi = v[r].y, di = d[r].y;
            r0.z = (ai + hi + vi + di) * 0.5f;
            r0.w = (ai + hi - vi - di) * 0.5f;
            r1.z = (ai - hi + vi - di) * 0.5f;
            r1.w = (ai - hi - vi + di) * 0.5f;
        }
        *(float4*)(o + (2 * r) * (2 * IWT_W))     = r0;  // row 2h0+2r
        *(float4*)(o + (2 * r + 1) * (2 * IWT_W)) = r1;  // row 2h0+2r+1
    }
}

extern "C" void kernel_launch(void* const* d_in, const int* in_sizes, int n_in,
                              void* d_out, int out_size) {
    const float* x = (const float*)d_in[0];
    float* out = (float*)d_out;

    // total input elems = 33,554,432 ; each thread consumes 32 elems
    int total = in_sizes[0];
    int threads_total = total / 32;     // 1,048,576

    int threads = 256;
    int blocks = threads_total / threads;   // 4096
    iwt_kernel<<<blocks, threads>>>(x, out);
}